// round 8
// baseline (speedup 1.0000x reference)
#include <cuda_runtime.h>

// OpenLSTM: B=4096 sequences, T=1024, HID=16, PROJ=2.
// t < 256 teacher-forced; t >= 256 recurrent.
//
// R8 = R5 (best, 191.5us) with the 16-lane shfl butterfly (8 SHFL + 8 ADD,
// 120cyc chain) replaced by fixed-point redux.sync.add.s32 all-reduce
// (CVT->REDUX->CVT, ~6 instr, ~70cyc chain). Scale 2^24 folded into weights:
// w_hr pre-scaled by 2^24 (producer), recurrent w_hh pre-scaled by 2^-24
// (consumer); teacher phase keeps unscaled w_hh (h input comes from data).
// Layout unchanged: TPE=16, 2 elem/warp, 2048 warps (3.46/SMSP).

#define T_TOTAL 1024
#define N_CTX   256
#define TPE     16
#define EPB     4     // elements per 64-thread block
#define TU      4     // teacher-phase time unroll
#define FSCALE     16777216.0f            // 2^24  (exact in f32)
#define INV_FSCALE 5.9604644775390625e-8f // 2^-24 (exact in f32)

__device__ __forceinline__ float tanh_fast(float x) {
    float y;
    asm("tanh.approx.f32 %0, %1;" : "=f"(y) : "f"(x));
    return y;
}

// Warp-segment integer add all-reduce (sm_80+). Disjoint 16-lane masks.
__device__ __forceinline__ int redux_add_s32(int v, unsigned mask) {
    int r;
    asm volatile("redux.sync.add.s32 %0, %1, %2;" : "=r"(r) : "r"(v), "r"(mask));
    return r;
}

__global__ void __launch_bounds__(64)
open_lstm_kernel(const float* __restrict__ u,     // (B, T, 4)
                 const float* __restrict__ w_ih,  // (64, 2)
                 const float* __restrict__ w_hh,  // (64, 2)
                 const float* __restrict__ b_ih,  // (64)
                 const float* __restrict__ b_hh,  // (64)
                 const float* __restrict__ w_hr,  // (2, 16)
                 float* __restrict__ out)         // (B, T, 2)
{
    const int tid  = threadIdx.x;
    const int j    = tid & (TPE - 1);                 // hidden unit 0..15
    const int e    = blockIdx.x * EPB + (tid >> 4);   // element index
    const unsigned rmask = 0xFFFFu << (tid & 16);     // this element's 16 lanes

    // Weights for unit j. sigma(x)=0.5*tanh(0.5x)+0.5 folded: i/f/o gate rows
    // pre-scaled by 0.5; o-path outer 0.5 folded into w_hr.
    // whT: teacher-phase h-weights (true scale, h comes from data).
    // whR: recurrent h-weights, pre-scaled by 2^-24 (consume scaled H).
    // wr0s/wr1s: w_hr * 0.5 * 2^24 (produce scaled projection partials).
    float wi[4][2], whT[4][2], whR[4][2], bb[4], wr0s, wr1s;
#pragma unroll
    for (int k = 0; k < 4; k++) {
        const int r = k * 16 + j;
        const float sc = (k == 2) ? 1.0f : 0.5f;
        wi[k][0]  = w_ih[r * 2 + 0] * sc;
        wi[k][1]  = w_ih[r * 2 + 1] * sc;
        whT[k][0] = w_hh[r * 2 + 0] * sc;
        whT[k][1] = w_hh[r * 2 + 1] * sc;
        whR[k][0] = whT[k][0] * INV_FSCALE;
        whR[k][1] = whT[k][1] * INV_FSCALE;
        bb[k]     = (b_ih[r] + b_hh[r]) * sc;
    }
    wr0s = w_hr[j]      * 0.5f * FSCALE;
    wr1s = w_hr[16 + j] * 0.5f * FSCALE;

    const float4* __restrict__ up = (const float4*)u + (size_t)e * T_TOTAL;
    float2* __restrict__ op       = (float2*)out + (size_t)e * T_TOTAL;

    float c = 0.0f;
    float H0 = 0.0f, H1 = 0.0f;   // scaled hidden state (true h * 2^24)

    // ================= teacher-forced phase, unrolled x4 =================
#pragma unroll 1
    for (int t = 0; t < N_CTX; t += TU) {
        float4 vv[TU];
#pragma unroll
        for (int s = 0; s < TU; s++) vv[s] = up[t + s];

        float gg[TU][4];
#pragma unroll
        for (int s = 0; s < TU; s++)
#pragma unroll
            for (int k = 0; k < 4; k++)
                gg[s][k] = fmaf(wi[k][0], vv[s].x,
                           fmaf(wi[k][1], vv[s].y,
                           fmaf(whT[k][0], vv[s].z,
                           fmaf(whT[k][1], vv[s].w, bb[k]))));

        float ti[TU], tf[TU], tg[TU], to[TU];
#pragma unroll
        for (int s = 0; s < TU; s++) {
            ti[s] = tanh_fast(gg[s][0]);
            tf[s] = tanh_fast(gg[s][1]);
            tg[s] = tanh_fast(gg[s][2]);
            to[s] = tanh_fast(gg[s][3]);
        }

        float tc[TU];
#pragma unroll
        for (int s = 0; s < TU; s++) {
            float ca = fmaf(tf[s], c, c);            // 2*sigma(f)*c
            float cb = fmaf(ti[s], tg[s], tg[s]);    // 2*sigma(i)*tanh(g)
            c = fmaf(0.5f, ca, 0.5f * cb);
            tc[s] = tanh_fast(c);
        }

        float h0v[TU], h1v[TU];
#pragma unroll
        for (int s = 0; s < TU; s++) {
            float b0 = fmaf(wr0s, to[s], wr0s);      // wr0*(1+to)*2^24
            float b1 = fmaf(wr1s, to[s], wr1s);
            int q0 = __float2int_rn(b0 * tc[s]);
            int q1 = __float2int_rn(b1 * tc[s]);
            h0v[s] = (float)redux_add_s32(q0, rmask);  // scaled sums
            h1v[s] = (float)redux_add_s32(q1, rmask);
        }
        if (j == 0) {
#pragma unroll
            for (int s = 0; s < TU; s++)
                op[t + s] = make_float2(h0v[s] * INV_FSCALE,
                                        h1v[s] * INV_FSCALE);
        }
        H0 = h0v[TU - 1];
        H1 = h1v[TU - 1];
    }

    // ================= recurrent phase =================
    float4 v = up[N_CTX];
    float xp[4];
#pragma unroll
    for (int k = 0; k < 4; k++)
        xp[k] = fmaf(wi[k][0], v.x, fmaf(wi[k][1], v.y, bb[k]));

#pragma unroll 2
    for (int t = N_CTX; t < T_TOTAL; t++) {
        float4 vn = up[(t + 1 < T_TOTAL) ? (t + 1) : t];

        // gates consume SCALED H via pre-scaled whR (chain: 2 FMA)
        float gi  = fmaf(whR[0][0], H0, fmaf(whR[0][1], H1, xp[0]));
        float gf  = fmaf(whR[1][0], H0, fmaf(whR[1][1], H1, xp[1]));
        float gg2 = fmaf(whR[2][0], H0, fmaf(whR[2][1], H1, xp[2]));
        float go  = fmaf(whR[3][0], H0, fmaf(whR[3][1], H1, xp[3]));

        float ti = tanh_fast(gi);
        float tf = tanh_fast(gf);
        float tg = tanh_fast(gg2);
        float to = tanh_fast(go);

        float ca = fmaf(tf, c, c);
        float cb = fmaf(ti, tg, tg);
        c = fmaf(0.5f, ca, 0.5f * cb);

        float tc = tanh_fast(c);
        float b0 = fmaf(wr0s, to, wr0s);   // off critical chain
        float b1 = fmaf(wr1s, to, wr1s);

        int q0 = __float2int_rn(b0 * tc);
        int q1 = __float2int_rn(b1 * tc);
        H0 = (float)redux_add_s32(q0, rmask);
        H1 = (float)redux_add_s32(q1, rmask);

        if (j == 0) op[t] = make_float2(H0 * INV_FSCALE, H1 * INV_FSCALE);

        // next step's x-part (off critical chain)
#pragma unroll
        for (int k = 0; k < 4; k++)
            xp[k] = fmaf(wi[k][0], vn.x, fmaf(wi[k][1], vn.y, bb[k]));
        v = vn;
    }
}

extern "C" void kernel_launch(void* const* d_in, const int* in_sizes, int n_in,
                              void* d_out, int out_size)
{
    const float* u    = (const float*)d_in[0];
    const float* w_ih = (const float*)d_in[1];
    const float* w_hh = (const float*)d_in[2];
    const float* b_ih = (const float*)d_in[3];
    const float* b_hh = (const float*)d_in[4];
    const float* w_hr = (const float*)d_in[5];
    float* out = (float*)d_out;

    const int B = in_sizes[0] / (T_TOTAL * 4);   // 4096
    const int grid = B / EPB;                    // 1024 blocks x 64 threads

    open_lstm_kernel<<<grid, 64>>>(u, w_ih, w_hh, b_ih, b_hh, w_hr, out);
}

// round 9
// speedup vs baseline: 2.1354x; 2.1354x over previous
#include <cuda_runtime.h>

// OpenLSTM: B=4096 sequences, T=1024, HID=16, PROJ=2.
// t < 256 teacher-forced; t >= 256 recurrent.
//
// R9 = R5 + segregated reduction (SHFL 8->5 recurrent, 8->4 teacher) + no
// store branch. Theory: SHFL throughput (rt~8 on MIO) is the floor -- R5
// teacher phase measured 210 cyc/step == 3.46 warps x 8 SHFL x rt8 = 221.
// Round 1: lanes 0-7 accumulate p0, 8-15 accumulate p1 (one shfl_xor(8) with
// selected send value); 3 tree rounds; store h.x from lanes<8 / h.y from
// lanes>=8 as scalar 4B stores (unconditional, no broadcast needed); one
// extra broadcast shfl only in the recurrent phase (gates need H0,H1).
// Layout unchanged: TPE=16, 2 elem/warp, 2048 warps (3.46/SMSP).

#define T_TOTAL 1024
#define N_CTX   256
#define TPE     16
#define EPB     4     // elements per 64-thread block
#define TU      4     // teacher-phase time unroll

__device__ __forceinline__ float tanh_fast(float x) {
    float y;
    asm("tanh.approx.f32 %0, %1;" : "=f"(y) : "f"(x));
    return y;
}

__global__ void __launch_bounds__(64)
open_lstm_kernel(const float* __restrict__ u,     // (B, T, 4)
                 const float* __restrict__ w_ih,  // (64, 2)
                 const float* __restrict__ w_hh,  // (64, 2)
                 const float* __restrict__ b_ih,  // (64)
                 const float* __restrict__ b_hh,  // (64)
                 const float* __restrict__ w_hr,  // (2, 16)
                 float* __restrict__ out)         // (B, T, 2)
{
    const int tid  = threadIdx.x;
    const int j    = tid & (TPE - 1);                 // hidden unit 0..15
    const int e    = blockIdx.x * EPB + (tid >> 4);   // element index
    const bool lo8 = (j < 8);                         // p0-side lane?

    // Weights for unit j. sigma(x)=0.5*tanh(0.5x)+0.5 folded: i/f/o gate rows
    // pre-scaled by 0.5; o-path outer 0.5 folded into w_hr.
    float wi[4][2], wh[4][2], bb[4], wr0, wr1;
#pragma unroll
    for (int k = 0; k < 4; k++) {
        const int r = k * 16 + j;
        const float sc = (k == 2) ? 1.0f : 0.5f;
        wi[k][0] = w_ih[r * 2 + 0] * sc;
        wi[k][1] = w_ih[r * 2 + 1] * sc;
        wh[k][0] = w_hh[r * 2 + 0] * sc;
        wh[k][1] = w_hh[r * 2 + 1] * sc;
        bb[k]    = (b_ih[r] + b_hh[r]) * sc;
    }
    wr0 = w_hr[j]      * 0.5f;
    wr1 = w_hr[16 + j] * 0.5f;

    const float4* __restrict__ up = (const float4*)u + (size_t)e * T_TOTAL;
    float* __restrict__ opf       = (float*)out + (size_t)e * T_TOTAL * 2;
    const int so = (j >> 3) & 1;   // 0: writes h.x, 1: writes h.y

    float c = 0.0f;
    float s_last = 0.0f;           // segregated h (p0 on lanes<8, p1 on lanes>=8)

    // ================= teacher-forced phase, unrolled x4 =================
    // 4 SHFL per step (segregate + 3 tree rounds); store straight from
    // segregated lanes, no broadcast, no branch.
#pragma unroll 1
    for (int t = 0; t < N_CTX; t += TU) {
        float4 vv[TU];
#pragma unroll
        for (int s = 0; s < TU; s++) vv[s] = up[t + s];

        float gg[TU][4];
#pragma unroll
        for (int s = 0; s < TU; s++)
#pragma unroll
            for (int k = 0; k < 4; k++)
                gg[s][k] = fmaf(wi[k][0], vv[s].x,
                           fmaf(wi[k][1], vv[s].y,
                           fmaf(wh[k][0], vv[s].z,
                           fmaf(wh[k][1], vv[s].w, bb[k]))));

        float ti[TU], tf[TU], tg[TU], to[TU];
#pragma unroll
        for (int s = 0; s < TU; s++) {
            ti[s] = tanh_fast(gg[s][0]);
            tf[s] = tanh_fast(gg[s][1]);
            tg[s] = tanh_fast(gg[s][2]);
            to[s] = tanh_fast(gg[s][3]);
        }

        float tc[TU];
#pragma unroll
        for (int s = 0; s < TU; s++) {
            float ca = fmaf(tf[s], c, c);            // 2*sigma(f)*c
            float cb = fmaf(ti[s], tg[s], tg[s]);    // 2*sigma(i)*tanh(g)
            c = fmaf(0.5f, ca, 0.5f * cb);
            tc[s] = tanh_fast(c);
        }

        float sr[TU];
#pragma unroll
        for (int s = 0; s < TU; s++) {
            float b0 = fmaf(wr0, to[s], wr0);        // wr0*(1+to)
            float b1 = fmaf(wr1, to[s], wr1);
            float p0 = b0 * tc[s];
            float p1 = b1 * tc[s];
            // segregate: lanes<8 keep p0 (recv partner's p0), lanes>=8 keep p1
            float send = lo8 ? p1 : p0;
            float keep = lo8 ? p0 : p1;
            float r = keep + __shfl_xor_sync(0xffffffffu, send, 8);
            r += __shfl_xor_sync(0xffffffffu, r, 1);
            r += __shfl_xor_sync(0xffffffffu, r, 2);
            r += __shfl_xor_sync(0xffffffffu, r, 4);
            sr[s] = r;
        }
        // unconditional scalar stores: lanes<8 write .x, lanes>=8 write .y
#pragma unroll
        for (int s = 0; s < TU; s++)
            opf[2 * (t + s) + so] = sr[s];
        s_last = sr[TU - 1];
    }

    // broadcast final teacher h into all lanes
    float oth = __shfl_xor_sync(0xffffffffu, s_last, 8);
    float H0 = lo8 ? s_last : oth;
    float H1 = lo8 ? oth : s_last;

    // ================= recurrent phase =================
    // 5 SHFL per step (segregate + 3 tree + 1 broadcast).
    float4 v = up[N_CTX];
    float xp[4];
#pragma unroll
    for (int k = 0; k < 4; k++)
        xp[k] = fmaf(wi[k][0], v.x, fmaf(wi[k][1], v.y, bb[k]));

#pragma unroll 2
    for (int t = N_CTX; t < T_TOTAL; t++) {
        float4 vn = up[(t + 1 < T_TOTAL) ? (t + 1) : t];

        float gi  = fmaf(wh[0][0], H0, fmaf(wh[0][1], H1, xp[0]));
        float gf  = fmaf(wh[1][0], H0, fmaf(wh[1][1], H1, xp[1]));
        float gg2 = fmaf(wh[2][0], H0, fmaf(wh[2][1], H1, xp[2]));
        float go  = fmaf(wh[3][0], H0, fmaf(wh[3][1], H1, xp[3]));

        float ti = tanh_fast(gi);
        float tf = tanh_fast(gf);
        float tg = tanh_fast(gg2);
        float to = tanh_fast(go);

        float ca = fmaf(tf, c, c);
        float cb = fmaf(ti, tg, tg);
        c = fmaf(0.5f, ca, 0.5f * cb);

        float tc = tanh_fast(c);
        float b0 = fmaf(wr0, to, wr0);   // off critical chain
        float b1 = fmaf(wr1, to, wr1);

        float p0 = b0 * tc;
        float p1 = b1 * tc;
        float send = lo8 ? p1 : p0;
        float keep = lo8 ? p0 : p1;
        float r = keep + __shfl_xor_sync(0xffffffffu, send, 8);
        r += __shfl_xor_sync(0xffffffffu, r, 1);
        r += __shfl_xor_sync(0xffffffffu, r, 2);
        r += __shfl_xor_sync(0xffffffffu, r, 4);

        // store from segregated lanes (independent of broadcast below)
        opf[2 * t + so] = r;

        // broadcast so every lane has (H0, H1) for next step's gates
        float o2 = __shfl_xor_sync(0xffffffffu, r, 8);
        H0 = lo8 ? r : o2;
        H1 = lo8 ? o2 : r;

        // next step's x-part (off critical chain)
#pragma unroll
        for (int k = 0; k < 4; k++)
            xp[k] = fmaf(wi[k][0], vn.x, fmaf(wi[k][1], vn.y, bb[k]));
        v = vn;
    }
}

extern "C" void kernel_launch(void* const* d_in, const int* in_sizes, int n_in,
                              void* d_out, int out_size)
{
    const float* u    = (const float*)d_in[0];
    const float* w_ih = (const float*)d_in[1];
    const float* w_hh = (const float*)d_in[2];
    const float* b_ih = (const float*)d_in[3];
    const float* b_hh = (const float*)d_in[4];
    const float* w_hr = (const float*)d_in[5];
    float* out = (float*)d_out;

    const int B = in_sizes[0] / (T_TOTAL * 4);   // 4096
    const int grid = B / EPB;                    // 1024 blocks x 64 threads

    open_lstm_kernel<<<grid, 64>>>(u, w_ih, w_hh, b_ih, b_hh, w_hr, out);
}